// round 2
// baseline (speedup 1.0000x reference)
#include <cuda_runtime.h>
#include <math.h>
#include <stdint.h>

#define NC 65
#define NG 22
#define MAXB 64
#define EPS 1e-8f
#define TILE 128
#define ROWPAD 68
#define THR_A 128

// ---- constants derived from AA64 = 'FFLLSSSSYY**CC*WLLLLPPPPHHQQRRRRIIIMTTTTNNKKSSRRVVVVAAAADDEEGGGG'
__constant__ int c_gid[NC] = {
    0,
    6,6, 11,11, 17,17,17,17, 21,21, 1,1, 3,3, 1, 20,
    11,11,11,11, 14,14,14,14, 8,8, 15,15, 16,16,16,16,
    9,9,9, 12, 18,18,18,18, 13,13, 10,10, 17,17, 16,16,
    19,19,19,19, 2,2,2,2, 4,4, 5,5, 7,7,7,7};
__constant__ float c_nsyn[NC] = {
    0.f,
    2,2, 6,6, 6,6,6,6, 2,2, 3,3, 2,2, 3, 1,
    6,6,6,6, 4,4,4,4, 2,2, 2,2, 6,6,6,6,
    3,3,3, 1, 4,4,4,4, 2,2, 2,2, 6,6, 6,6,
    4,4,4,4, 4,4,4,4, 2,2, 2,2, 4,4,4,4};

// ---- global scratch (no allocs allowed)
__device__ float g_lwp[MAXB], g_lwt[MAXB];
__device__ int   g_maskc[MAXB];
__device__ int   g_cntp[MAXB][NC], g_cntt[MAXB][NC];
__device__ int   g_obsp[MAXB][NC], g_obst[MAXB][NC];
__device__ float g_ce_sum;
__device__ int   g_ce_cnt;
__device__ float g_cai, g_rscu, g_gc, g_dyn, g_str;

__global__ void zero_kernel() {
    int i = blockIdx.x * blockDim.x + threadIdx.x;
    const int tot = MAXB * NC;
    if (i < tot) {
        ((int*)g_cntp)[i] = 0; ((int*)g_cntt)[i] = 0;
        ((int*)g_obsp)[i] = 0; ((int*)g_obst)[i] = 0;
    }
    if (i < MAXB) { g_lwp[i] = 0.f; g_lwt[i] = 0.f; g_maskc[i] = 0; }
    if (i == 0) {
        g_ce_sum = 0.f; g_ce_cnt = 0;
        g_cai = 0.f; g_rscu = 0.f; g_gc = 0.f; g_dyn = 0.f; g_str = 0.f;
    }
}

// ------------- Phase A: heavy pass over logits -------------
__global__ void __launch_bounds__(THR_A) phaseA(
    const float* __restrict__ logits, const float* __restrict__ wmat,
    const int* __restrict__ tgt, const int* __restrict__ aa,
    const int* __restrict__ species, const unsigned char* __restrict__ mask,
    int L)
{
    int b  = blockIdx.y;
    int l0 = blockIdx.x * TILE;
    int tid = threadIdx.x;

    extern __shared__ float smem[];
    float* s_tile = smem;                 // TILE * ROWPAD floats
    float* s_logw = smem + TILE * ROWPAD; // NC floats

    __shared__ int   s_cntp[NC], s_cntt[NC], s_obsp[NC], s_obst[NC];
    __shared__ float s_ce, s_lwp, s_lwt;
    __shared__ int   s_cec, s_maskc;

    if (tid < NC) {
        int sp = species[b];
        s_logw[tid] = __logf(fmaxf(wmat[sp * NC + tid], EPS));
        s_cntp[tid] = 0; s_cntt[tid] = 0; s_obsp[tid] = 0; s_obst[tid] = 0;
    }
    if (tid == 0) { s_ce = 0.f; s_lwp = 0.f; s_lwt = 0.f; s_cec = 0; s_maskc = 0; }

    // Stage tile: contiguous 128*65 floats -> padded SMEM rows (ROWPAD=68)
    const float* gbase = logits + ((size_t)b * L + l0) * NC;
    const float4* g4 = (const float4*)gbase;
    const int NV = TILE * NC / 4; // 2080, exact (128*65 % 4 == 0)
    for (int v = tid; v < NV; v += THR_A) {
        float4 f = g4[v];
        int i0 = 4 * v;
        #pragma unroll
        for (int k = 0; k < 4; ++k) {
            int i = i0 + k;
            int r = i / NC;
            int c = i - r * NC;
            s_tile[r * ROWPAD + c] = (&f.x)[k];
        }
    }
    __syncthreads();

    // One thread per row: serial max/argmax + sum-exp (no shuffles)
    const float* row = s_tile + tid * ROWPAD;
    float4 q[16];
    #pragma unroll
    for (int i = 0; i < 16; ++i) q[i] = ((const float4*)row)[i];
    float v64 = row[64];

    float mx = -INFINITY; int am = 0;
    #pragma unroll
    for (int i = 0; i < 16; ++i) {
        #pragma unroll
        for (int k = 0; k < 4; ++k) {
            float v = (&q[i].x)[k];
            if (v > mx) { mx = v; am = 4 * i + k; }  // strict > => first index (jnp.argmax)
        }
    }
    if (v64 > mx) { mx = v64; am = 64; }

    float s = 0.f;
    #pragma unroll
    for (int i = 0; i < 16; ++i) {
        #pragma unroll
        for (int k = 0; k < 4; ++k) s += __expf((&q[i].x)[k] - mx);
    }
    s += __expf(v64 - mx);

    size_t gi = (size_t)b * L + l0 + tid;
    int t  = tgt[gi];
    int a  = aa[gi];
    int mk = mask[gi];

    float tl  = row[t];
    float nll = mx + __logf(s) - tl;

    if (t != 0) { atomicAdd(&s_ce, nll); atomicAdd(&s_cec, 1); }
    if (mk) {
        atomicAdd(&s_maskc, 1);
        atomicAdd(&s_lwp, s_logw[am]);
        atomicAdd(&s_lwt, s_logw[t]);
        if (am > 0) { atomicAdd(&s_cntp[am], 1); if (a > 2) s_obsp[am] = 1; }
        if (t  > 0) { atomicAdd(&s_cntt[t], 1);  if (a > 2) s_obst[t]  = 1; }
    }
    __syncthreads();

    if (tid < NC) {
        if (s_cntp[tid]) atomicAdd(&g_cntp[b][tid], s_cntp[tid]);
        if (s_cntt[tid]) atomicAdd(&g_cntt[b][tid], s_cntt[tid]);
        if (s_obsp[tid]) g_obsp[b][tid] = 1;   // idempotent
        if (s_obst[tid]) g_obst[b][tid] = 1;
    }
    if (tid == 0) {
        atomicAdd(&g_ce_sum, s_ce);
        atomicAdd(&g_ce_cnt, s_cec);
        atomicAdd(&g_lwp[b], s_lwp);
        atomicAdd(&g_lwt[b], s_lwt);
        atomicAdd(&g_maskc[b], s_maskc);
    }
}

// ------------- Phase B: per-batch RSCU KL + CAI -------------
__global__ void phaseB(const float* __restrict__ refdist,
                       const int* __restrict__ species)
{
    int b = blockIdx.x;
    int tid = threadIdx.x;
    __shared__ float gs_p[NG], gs_t[NG];
    __shared__ float s_p[NC], s_t[NC];

    if (tid < NG) { gs_p[tid] = 0.f; gs_t[tid] = 0.f; }
    __syncthreads();

    float ocp = 0.f, oct = 0.f;
    int op = 0, ot = 0, gid = 0;
    if (tid < NC) {
        gid = c_gid[tid];
        bool coding = (tid != 0) && (tid != 11) && (tid != 12) && (tid != 15);
        op = g_obsp[b][tid] && coding;
        ot = g_obst[b][tid] && coding;
        ocp = op ? (float)g_cntp[b][tid] : 0.f;
        oct = ot ? (float)g_cntt[b][tid] : 0.f;
        atomicAdd(&gs_p[gid], ocp);
        atomicAdd(&gs_t[gid], oct);
    }
    __syncthreads();

    if (tid < NC) {
        float totp = gs_p[gid], tott = gs_t[gid];
        float ns = c_nsyn[tid];
        float rp = (op && totp > 0.f) ? ocp * ns / fmaxf(totp, 1.f) : 0.f;
        float rt = (ot && tott > 0.f) ? oct * ns / fmaxf(tott, 1.f) : 0.f;
        s_p[tid] = rp + EPS;
        int sp = species[b];
        s_t[tid] = 0.7f * rt + 0.3f * refdist[sp * NC + tid] + EPS;
    }
    __syncthreads();

    if (tid == 0) {
        float sp_ = 0.f, st_ = 0.f;
        for (int c = 0; c < NC; ++c) { sp_ += s_p[c]; st_ += s_t[c]; }
        float kl = 0.f;
        for (int c = 0; c < NC; ++c) {
            float tt = s_t[c] / st_;
            float pp = s_p[c] / sp_;
            kl += tt * (logf(tt) - logf(pp));
        }
        atomicAdd(&g_rscu, kl);
        float denom = fmaxf((float)g_maskc[b], 1.f);
        float pc = expf(g_lwp[b] / denom);
        float tc = expf(g_lwt[b] / denom);
        atomicAdd(&g_cai, fmaxf(tc - pc, 0.f));
    }
}

// ------------- Phase C: gc / pause / mfe -------------
__global__ void phaseC(const float* __restrict__ gc,
                       const float* __restrict__ pause,
                       const float* __restrict__ mfe, int L)
{
    int b = blockIdx.x;
    int tid = threadIdx.x;
    __shared__ float rg[256], rp[256];

    const float4* g4 = (const float4*)(gc + (size_t)b * L);
    const float4* p4 = (const float4*)(pause + (size_t)b * L);
    float sg = 0.f, sp = 0.f;
    for (int v = tid; v < L / 4; v += 256) {
        float4 x = g4[v]; sg += x.x + x.y + x.z + x.w;
        float4 y = p4[v]; sp += y.x + y.y + y.z + y.w;
    }
    rg[tid] = sg; rp[tid] = sp;
    __syncthreads();
    for (int off = 128; off > 0; off >>= 1) {
        if (tid < off) { rg[tid] += rg[tid + off]; rp[tid] += rp[tid + off]; }
        __syncthreads();
    }
    if (tid == 0) {
        float gm = rg[0] / (float)L - 0.5f;
        float pm = rp[0] / (float)L - 0.1f;
        atomicAdd(&g_gc,  gm * gm);
        atomicAdd(&g_dyn, pm * pm);
        float sd = mfe[b] + 20.f;
        atomicAdd(&g_str, sd * sd);
    }
}

// ------------- Final combine -------------
__global__ void finalK(float* __restrict__ out, int B)
{
    float ce = g_ce_sum / fmaxf((float)g_ce_cnt, 1.f);
    float invB = 1.f / (float)B;
    out[0] = 1.0f  * ce
           + 0.4f  * g_cai  * invB
           + 0.3f  * g_rscu * invB
           + 0.1f  * g_gc   * invB
           + 0.15f * g_str  * invB
           + 0.1f  * g_dyn  * invB;
}

extern "C" void kernel_launch(void* const* d_in, const int* in_sizes, int n_in,
                              void* d_out, int out_size)
{
    const float* logits  = (const float*)d_in[0];
    const float* wmat    = (const float*)d_in[1];
    const float* refd    = (const float*)d_in[2];
    const float* gc      = (const float*)d_in[3];
    const float* mfe     = (const float*)d_in[4];
    const float* pause   = (const float*)d_in[5];
    const int*   tgt     = (const int*)d_in[6];
    const int*   aa      = (const int*)d_in[7];
    const int*   species = (const int*)d_in[8];
    const unsigned char* mask = (const unsigned char*)d_in[9];

    int B = in_sizes[4];             // mfe has B elements
    int L = in_sizes[3] / B;         // gc_pred has B*L elements

    zero_kernel<<<(MAXB * NC + 255) / 256, 256>>>();

    dim3 gridA(L / TILE, B);
    size_t smemA = (TILE * ROWPAD + NC) * sizeof(float);
    phaseA<<<gridA, THR_A, smemA>>>(logits, wmat, tgt, aa, species, mask, L);

    phaseB<<<B, 128>>>(refd, species);
    phaseC<<<B, 256>>>(gc, pause, mfe, L);
    finalK<<<1, 1>>>((float*)d_out, B);
}

// round 5
// speedup vs baseline: 1.5674x; 1.5674x over previous
#include <cuda_runtime.h>
#include <math.h>
#include <stdint.h>

#define NC 65
#define NG 22
#define MAXB 64
#define EPS 1e-8f
#define TILE 128
#define THR_A 128

// ---- constants derived from AA64 = 'FFLLSSSSYY**CC*WLLLLPPPPHHQQRRRRIIIMTTTTNNKKSSRRVVVVAAAADDEEGGGG'
__constant__ int c_gid[NC] = {
    0,
    6,6, 11,11, 17,17,17,17, 21,21, 1,1, 3,3, 1, 20,
    11,11,11,11, 14,14,14,14, 8,8, 15,15, 16,16,16,16,
    9,9,9, 12, 18,18,18,18, 13,13, 10,10, 17,17, 16,16,
    19,19,19,19, 2,2,2,2, 4,4, 5,5, 7,7,7,7};
__constant__ float c_nsyn[NC] = {
    0.f,
    2,2, 6,6, 6,6,6,6, 2,2, 3,3, 2,2, 3, 1,
    6,6,6,6, 4,4,4,4, 2,2, 2,2, 6,6,6,6,
    3,3,3, 1, 4,4,4,4, 2,2, 2,2, 6,6, 6,6,
    4,4,4,4, 4,4,4,4, 2,2, 2,2, 4,4,4,4};

// ---- global scratch (no allocs allowed)
__device__ double g_lwp[MAXB], g_lwt[MAXB];
__device__ double g_gcs[MAXB], g_pps[MAXB];
__device__ int    g_maskc[MAXB];
__device__ int    g_cntp[MAXB][NC], g_cntt[MAXB][NC];
__device__ int    g_obsp[MAXB][NC], g_obst[MAXB][NC];
__device__ double g_ce_sum;
__device__ int    g_ce_cnt;
__device__ double g_rscu, g_cai;

__global__ void zeroK() {
    int i = blockIdx.x * blockDim.x + threadIdx.x;
    if (i < MAXB * NC) {
        ((int*)g_cntp)[i] = 0; ((int*)g_cntt)[i] = 0;
        ((int*)g_obsp)[i] = 0; ((int*)g_obst)[i] = 0;
    }
    if (i < MAXB) {
        g_lwp[i] = 0.0; g_lwt[i] = 0.0;
        g_gcs[i] = 0.0; g_pps[i] = 0.0;
        g_maskc[i] = 0;
    }
    if (i == 0) { g_ce_sum = 0.0; g_ce_cnt = 0; g_rscu = 0.0; g_cai = 0.0; }
}

// ------------- Phase A: heavy pass over logits + gc/pause fold-in -------------
__global__ void __launch_bounds__(THR_A) phaseA(
    const float* __restrict__ logits, const float* __restrict__ wmat,
    const float* __restrict__ gc,     const float* __restrict__ pause,
    const int* __restrict__ tgt,      const int* __restrict__ aa,
    const int* __restrict__ species,  const unsigned char* __restrict__ mask,
    int L)
{
    int b   = blockIdx.y;
    int l0  = blockIdx.x * TILE;
    int tid = threadIdx.x;
    int wid = tid >> 5, lane = tid & 31;

    extern __shared__ float smem[];
    float* s_tile = smem;                // TILE*NC floats, global layout (no pad)
    float* s_logw = smem + TILE * NC;    // NC floats

    __shared__ int   s_cntp[NC], s_cntt[NC], s_obsp[NC], s_obst[NC];
    __shared__ float r_ce[4], r_lwp[4], r_lwt[4];
    __shared__ int   r_cec[4], r_mk[4];
    __shared__ float r_gc, r_pp;

    if (tid < NC) {
        int sp = species[b];
        s_logw[tid] = __logf(fmaxf(wmat[sp * NC + tid], EPS));
        s_cntp[tid] = 0; s_cntt[tid] = 0; s_obsp[tid] = 0; s_obst[tid] = 0;
    }

    // Stage tile: pure float4 copy, identical layout to global
    {
        const float4* g4 = (const float4*)(logits + ((size_t)b * L + l0) * NC);
        float4* s4 = (float4*)s_tile;
        #pragma unroll 4
        for (int v = tid; v < TILE * NC / 4; v += THR_A) s4[v] = g4[v];
    }

    // gc / pause segment sums (warp 0 covers TILE floats of each)
    if (wid == 0) {
        const float4* gp = (const float4*)(gc    + (size_t)b * L + l0);
        const float4* pp = (const float4*)(pause + (size_t)b * L + l0);
        float4 x = gp[lane], y = pp[lane];
        float sg = x.x + x.y + x.z + x.w;
        float sp = y.x + y.y + y.z + y.w;
        #pragma unroll
        for (int o = 16; o; o >>= 1) {
            sg += __shfl_xor_sync(0xffffffffu, sg, o);
            sp += __shfl_xor_sync(0xffffffffu, sp, o);
        }
        if (lane == 0) { r_gc = sg; r_pp = sp; }
    }

    size_t gi = (size_t)b * L + l0 + tid;
    int t  = tgt[gi];
    int a  = aa[gi];
    int mk = mask[gi];

    __syncthreads();

    // One thread per row; stride-65 scalar LDS is bank-conflict-free
    const float* row = s_tile + tid * NC;

    float mx = row[0]; int am = 0;
    #pragma unroll
    for (int c = 1; c < NC; ++c) {
        float v = row[c];
        if (v > mx) { mx = v; am = c; }   // strict > => first index (jnp.argmax)
    }
    float ssum = 0.f;
    #pragma unroll
    for (int c = 0; c < NC; ++c) ssum += __expf(row[c] - mx);

    float nll = mx + __logf(ssum) - row[t];

    float ce  = (t != 0) ? nll : 0.f;
    float lwp = 0.f, lwt = 0.f;
    if (mk) {
        lwp = s_logw[am];
        lwt = s_logw[t];
        if (am > 0) { atomicAdd(&s_cntp[am], 1); if (a > 2) s_obsp[am] = 1; }
        if (t  > 0) { atomicAdd(&s_cntt[t], 1);  if (a > 2) s_obst[t]  = 1; }
    }
    #pragma unroll
    for (int o = 16; o; o >>= 1) {
        ce  += __shfl_xor_sync(0xffffffffu, ce,  o);
        lwp += __shfl_xor_sync(0xffffffffu, lwp, o);
        lwt += __shfl_xor_sync(0xffffffffu, lwt, o);
    }
    int cecw = __popc(__ballot_sync(0xffffffffu, t != 0));
    int mkw  = __popc(__ballot_sync(0xffffffffu, mk != 0));
    if (lane == 0) { r_ce[wid] = ce; r_lwp[wid] = lwp; r_lwt[wid] = lwt; r_cec[wid] = cecw; r_mk[wid] = mkw; }
    __syncthreads();

    if (tid < NC) {
        int cp = s_cntp[tid], ct = s_cntt[tid];
        if (cp) atomicAdd(&g_cntp[b][tid], cp);
        if (ct) atomicAdd(&g_cntt[b][tid], ct);
        if (s_obsp[tid]) g_obsp[b][tid] = 1;   // idempotent
        if (s_obst[tid]) g_obst[b][tid] = 1;
    }
    if (tid == 0) {
        float ceS  = r_ce[0]  + r_ce[1]  + r_ce[2]  + r_ce[3];
        float lwpS = r_lwp[0] + r_lwp[1] + r_lwp[2] + r_lwp[3];
        float lwtS = r_lwt[0] + r_lwt[1] + r_lwt[2] + r_lwt[3];
        int   cecS = r_cec[0] + r_cec[1] + r_cec[2] + r_cec[3];
        int   mkS  = r_mk[0]  + r_mk[1]  + r_mk[2]  + r_mk[3];
        atomicAdd(&g_ce_sum, (double)ceS);
        atomicAdd(&g_ce_cnt, cecS);
        atomicAdd(&g_lwp[b], (double)lwpS);
        atomicAdd(&g_lwt[b], (double)lwtS);
        atomicAdd(&g_maskc[b], mkS);
        atomicAdd(&g_gcs[b], (double)r_gc);
        atomicAdd(&g_pps[b], (double)r_pp);
    }
}

// ------------- Phase B: per-batch RSCU KL + CAI (parallel over 65 lanes) -------------
__global__ void phaseB(const float* __restrict__ refd,
                       const int* __restrict__ species)
{
    int b = blockIdx.x;
    int tid = threadIdx.x;
    __shared__ float gs_p[NG], gs_t[NG];
    __shared__ float sum_p, sum_t;
    __shared__ double kl_acc;

    if (tid < NG) { gs_p[tid] = 0.f; gs_t[tid] = 0.f; }
    if (tid == 0) { sum_p = 0.f; sum_t = 0.f; kl_acc = 0.0; }
    __syncthreads();

    int gid = 0, op = 0, ot = 0;
    float ocp = 0.f, oct = 0.f;
    if (tid < NC) {
        gid = c_gid[tid];
        bool coding = (tid != 0) && (tid != 11) && (tid != 12) && (tid != 15);
        op = g_obsp[b][tid] && coding;
        ot = g_obst[b][tid] && coding;
        ocp = op ? (float)g_cntp[b][tid] : 0.f;
        oct = ot ? (float)g_cntt[b][tid] : 0.f;
        atomicAdd(&gs_p[gid], ocp);
        atomicAdd(&gs_t[gid], oct);
    }
    __syncthreads();

    float pterm = 0.f, tterm = 0.f;
    if (tid < NC) {
        float totp = gs_p[gid], tott = gs_t[gid];
        float ns = c_nsyn[tid];
        float rp = (op && totp > 0.f) ? ocp * ns / fmaxf(totp, 1.f) : 0.f;
        float rt = (ot && tott > 0.f) ? oct * ns / fmaxf(tott, 1.f) : 0.f;
        pterm = rp + EPS;
        int sp = species[b];
        tterm = 0.7f * rt + 0.3f * refd[sp * NC + tid] + EPS;
        atomicAdd(&sum_p, pterm);
        atomicAdd(&sum_t, tterm);
    }
    __syncthreads();

    if (tid < NC) {
        double tt = (double)tterm / (double)sum_t;
        double pp = (double)pterm / (double)sum_p;
        atomicAdd(&kl_acc, tt * (log(tt) - log(pp)));
    }
    __syncthreads();

    if (tid == 0) {
        atomicAdd(&g_rscu, kl_acc);
        double denom = fmax((double)g_maskc[b], 1.0);
        double pc = exp(g_lwp[b] / denom);
        double tc = exp(g_lwt[b] / denom);
        atomicAdd(&g_cai, fmax(tc - pc, 0.0));
    }
}

// ------------- Final combine -------------
__global__ void finalK(float* __restrict__ out,
                       const float* __restrict__ mfe, int B, int L)
{
    int tid = threadIdx.x;
    double gcv = 0.0, dyv = 0.0, stv = 0.0;
    if (tid < B) {
        double gm = g_gcs[tid] / (double)L - 0.5;
        double pm = g_pps[tid] / (double)L - 0.1;
        double sd = (double)mfe[tid] + 20.0;
        gcv = gm * gm; dyv = pm * pm; stv = sd * sd;
    }
    #pragma unroll
    for (int o = 16; o; o >>= 1) {
        gcv += __shfl_xor_sync(0xffffffffu, gcv, o);
        dyv += __shfl_xor_sync(0xffffffffu, dyv, o);
        stv += __shfl_xor_sync(0xffffffffu, stv, o);
    }
    __shared__ double sh[3][2];
    int wid = tid >> 5, lane = tid & 31;
    if (lane == 0) { sh[0][wid] = gcv; sh[1][wid] = dyv; sh[2][wid] = stv; }
    __syncthreads();
    if (tid == 0) {
        double gct = sh[0][0] + sh[0][1];
        double dyt = sh[1][0] + sh[1][1];
        double stt = sh[2][0] + sh[2][1];
        double invB = 1.0 / (double)B;
        double ce = g_ce_sum / fmax((double)g_ce_cnt, 1.0);
        out[0] = (float)(ce
                       + 0.4  * g_cai  * invB
                       + 0.3  * g_rscu * invB
                       + 0.1  * gct    * invB
                       + 0.15 * stt    * invB
                       + 0.1  * dyt    * invB);
    }
}

extern "C" void kernel_launch(void* const* d_in, const int* in_sizes, int n_in,
                              void* d_out, int out_size)
{
    const float* logits  = (const float*)d_in[0];
    const float* wmat    = (const float*)d_in[1];
    const float* refd    = (const float*)d_in[2];
    const float* gc      = (const float*)d_in[3];
    const float* mfe     = (const float*)d_in[4];
    const float* pause   = (const float*)d_in[5];
    const int*   tgt     = (const int*)d_in[6];
    const int*   aa      = (const int*)d_in[7];
    const int*   species = (const int*)d_in[8];
    const unsigned char* mask = (const unsigned char*)d_in[9];

    int B = in_sizes[4];             // mfe has B elements
    int L = in_sizes[3] / B;         // gc_pred has B*L elements

    zeroK<<<(MAXB * NC + 255) / 256, 256>>>();

    dim3 gridA(L / TILE, B);
    size_t smemA = (TILE * NC + NC) * sizeof(float);
    phaseA<<<gridA, THR_A, smemA>>>(logits, wmat, gc, pause, tgt, aa, species, mask, L);

    phaseB<<<B, 96>>>(refd, species);
    finalK<<<1, 64>>>((float*)d_out, mfe, B, L);
}